// round 16
// baseline (speedup 1.0000x reference)
#include <cuda_runtime.h>
#include <cuda_pipeline.h>

#define SS 4096
#define HH 2048
#define EE 8
#define CAP 512
#define NTOK 32768
#define DD (NTOK*EE)          /* 262144 */
#define K1_GRID 256           /* 256 blocks x 128 tokens */
#define STAGES 3
#define SMEM_BYTES (65536 + STAGES*16384)   /* W + stage ring = 112KB */

typedef unsigned long long u64;

__device__ float g_part[1024];          // per-K1-block loss partials (512 used)
__device__ unsigned char g_eid[NTOK];   // argmax expert per token
__device__ float g_w[NTOK];             // max prob per token
__device__ int g_cnt[64 * 8];           // [row*8+chunk][expert] counts

__device__ __forceinline__ void ffma2(u64 &acc, u64 a, u64 b) {
    asm("fma.rn.f32x2 %0, %1, %2, %0;" : "+l"(acc) : "l"(a), "l"(b));
}
__device__ __forceinline__ u64 packf2(float a, float b) {
    return (u64)__float_as_uint(a) | ((u64)__float_as_uint(b) << 32);
}
__device__ __forceinline__ float f_lo(u64 v) { return __uint_as_float((unsigned)v); }
__device__ __forceinline__ float f_hi(u64 v) { return __uint_as_float((unsigned)(v >> 32)); }

__device__ __forceinline__ void token_epilogue(const float* lg, float* __restrict__ probs_out,
                                               long tok, float& aux, float& zz) {
    float m = lg[0];
#pragma unroll
    for (int e = 1; e < 8; e++) m = fmaxf(m, lg[e]);
    float p[8];
    float s = 0.f;
#pragma unroll
    for (int e = 0; e < 8; e++) { p[e] = __expf(lg[e] - m); s += p[e]; }
    float inv = 1.f / s;
    float psq = 0.f;
#pragma unroll
    for (int e = 0; e < 8; e++) { p[e] *= inv; psq += p[e] * p[e]; }
    float4* o = (float4*)(probs_out + (size_t)tok * 8);
    o[0] = make_float4(p[0], p[1], p[2], p[3]);
    o[1] = make_float4(p[4], p[5], p[6], p[7]);
    float lse = m + __logf(s);
    aux += psq;
    zz += lse * lse;
}

// ---------------------------------------------------------------------------
// Kernel 1: logits GEMM + softmax + probs + loss partials.
// grid 256, block 256. Block = 128 tokens. Thread = 4 tokens x 256-wide K seg.
// Hidden staged through smem with a 3-deep cp.async pipeline (16KB stages);
// W resident in smem (paired f32x2 layout). Accumulators in registers.
// ---------------------------------------------------------------------------
__global__ __launch_bounds__(256, 2) void router_kernel(const float* __restrict__ hid,
                                                        const float* __restrict__ W,
                                                        float* __restrict__ probs_out) {
    extern __shared__ ulonglong2 smem[];
    ulonglong2* swp = smem;               // [e*512 + q]: W[4q..4q+3][e] (64KB)
    ulonglong2* sh  = smem + 4096;        // stage ring: [st][tok][seg] (3x16KB)

    int tid = threadIdx.x;
    for (int idx = tid; idx < 4096; idx += 256) {
        int e = idx >> 9;
        int q = idx & 511;
        int h = q * 4;
        ulonglong2 v;
        v.x = packf2(W[(h + 0) * 8 + e], W[(h + 1) * 8 + e]);
        v.y = packf2(W[(h + 2) * 8 + e], W[(h + 3) * 8 + e]);
        swp[idx] = v;
    }

    int kseg = tid & 7;
    int slot = tid >> 3;   // 0..31 -> token quad
    int wid  = tid >> 5;
    long tokB = (long)blockIdx.x * 128;   // block token base

    const float* hbase = hid + (size_t)tokB * HH;

    // producer helper (all threads): stage s <- h-chunk [s*32, s*32+32) of 128 tokens
    auto load_stage = [&](int s) {
        ulonglong2* dst = sh + (s % STAGES) * 1024;
#pragma unroll
        for (int k = 0; k < 4; k++) {
            int idx = tid + k * 256;          // 0..1023
            int tok = idx >> 3;
            int seg = idx & 7;
            __pipeline_memcpy_async(&dst[tok * 8 + seg],
                                    hbase + (size_t)tok * HH + s * 32 + seg * 4, 16);
        }
        __pipeline_commit();
    };

    load_stage(0);
    load_stage(1);
    __syncthreads();   // W layout also ready after this

    u64 acc0[8] = {0,0,0,0,0,0,0,0};
    u64 acc1[8] = {0,0,0,0,0,0,0,0};
    u64 acc2[8] = {0,0,0,0,0,0,0,0};
    u64 acc3[8] = {0,0,0,0,0,0,0,0};

    int t0 = slot * 4;
    for (int i = 0; i < 64; i++) {
        if (i < 62) __pipeline_wait_prior(1);
        else        __pipeline_wait_prior(0);
        __syncthreads();                       // stage i visible; stage (i+2)%3 free
        if (i + 2 < 64) load_stage(i + 2);

        const ulonglong2* st = sh + (i % STAGES) * 1024;
        ulonglong2 c0 = st[(t0 + 0) * 8 + kseg];
        ulonglong2 c1 = st[(t0 + 1) * 8 + kseg];
        ulonglong2 c2 = st[(t0 + 2) * 8 + kseg];
        ulonglong2 c3 = st[(t0 + 3) * 8 + kseg];
        const ulonglong2* ws = &swp[kseg + 8 * i];
#pragma unroll
        for (int e = 0; e < 8; e++) {
            ulonglong2 w = ws[e * 512];
            ffma2(acc0[e], c0.x, w.x);  ffma2(acc0[e], c0.y, w.y);
            ffma2(acc1[e], c1.x, w.x);  ffma2(acc1[e], c1.y, w.y);
            ffma2(acc2[e], c2.x, w.x);  ffma2(acc2[e], c2.y, w.y);
            ffma2(acc3[e], c3.x, w.x);  ffma2(acc3[e], c3.y, w.y);
        }
    }

    float lg0[8], lg1[8], lg2[8], lg3[8];
#pragma unroll
    for (int e = 0; e < 8; e++) {
        lg0[e] = f_lo(acc0[e]) + f_hi(acc0[e]);
        lg1[e] = f_lo(acc1[e]) + f_hi(acc1[e]);
        lg2[e] = f_lo(acc2[e]) + f_hi(acc2[e]);
        lg3[e] = f_lo(acc3[e]) + f_hi(acc3[e]);
    }
#pragma unroll
    for (int off = 4; off; off >>= 1) {
#pragma unroll
        for (int e = 0; e < 8; e++) {
            lg0[e] += __shfl_down_sync(0xffffffffu, lg0[e], off, 8);
            lg1[e] += __shfl_down_sync(0xffffffffu, lg1[e], off, 8);
            lg2[e] += __shfl_down_sync(0xffffffffu, lg2[e], off, 8);
            lg3[e] += __shfl_down_sync(0xffffffffu, lg3[e], off, 8);
        }
    }

    float auxAcc = 0.f, zAcc = 0.f;
    if (kseg == 0) {
        long tok0 = tokB + (long)slot * 4;
        token_epilogue(lg0, probs_out, tok0 + 0, auxAcc, zAcc);
        token_epilogue(lg1, probs_out, tok0 + 1, auxAcc, zAcc);
        token_epilogue(lg2, probs_out, tok0 + 2, auxAcc, zAcc);
        token_epilogue(lg3, probs_out, tok0 + 3, auxAcc, zAcc);
    }

#pragma unroll
    for (int off = 16; off; off >>= 1) {
        auxAcc += __shfl_down_sync(0xffffffffu, auxAcc, off);
        zAcc   += __shfl_down_sync(0xffffffffu, zAcc, off);
    }
    __shared__ float sA[8], sB[8];
    if ((tid & 31) == 0) { sA[wid] = auxAcc; sB[wid] = zAcc; }
    __syncthreads();
    if (tid == 0) {
        float a = 0.f, z = 0.f;
#pragma unroll
        for (int w = 0; w < 8; w++) { a += sA[w]; z += sB[w]; }
        g_part[blockIdx.x * 2 + 0] = a;
        g_part[blockIdx.x * 2 + 1] = z;
    }
}

// ---------------------------------------------------------------------------
// Kernel 2a: argmax + per-chunk expert counts (grid 64 = 8 rows x 8 chunks),
// plus fused loss reduction in block 0.
// ---------------------------------------------------------------------------
__global__ __launch_bounds__(512) void argmax_kernel(const float* __restrict__ probs,
                                                     float* __restrict__ out) {
    int b = blockIdx.x;
    int row = b >> 3, chunk = b & 7;
    int t = threadIdx.x;
    __shared__ int scnt[8];
    if (t < 8) scnt[t] = 0;
    __syncthreads();

    int tokr = chunk * 512 + t;
    int gi = row * SS + tokr;
    const float4* pr = (const float4*)(probs + (size_t)gi * 8);
    float4 lo = pr[0];
    float4 hi = pr[1];
    float v[8] = {lo.x, lo.y, lo.z, lo.w, hi.x, hi.y, hi.z, hi.w};
    float m = v[0];
    int mi = 0;
#pragma unroll
    for (int e = 1; e < 8; e++)
        if (v[e] > m) { m = v[e]; mi = e; }
    g_eid[gi] = (unsigned char)mi;
    g_w[gi] = m;
    atomicAdd(&scnt[mi], 1);
    __syncthreads();
    if (t < 8) g_cnt[b * 8 + t] = scnt[t];

    // fused loss reduction (K1 grid = 256 -> 512 partial floats)
    if (b == 0) {
        __shared__ float rA[256], rB[256];
        if (t < 256) { rA[t] = g_part[t * 2]; rB[t] = g_part[t * 2 + 1]; }
        __syncthreads();
        for (int off = 128; off; off >>= 1) {
            if (t < off) { rA[t] += rA[t + off]; rB[t] += rB[t + off]; }
            __syncthreads();
        }
        if (t == 0) {
            out[3 * (size_t)DD + 0] = rA[0] * ((float)EE / (float)NTOK);  // aux_loss
            out[3 * (size_t)DD + 1] = rB[0] / (float)NTOK;                // z_loss
        }
    }
}

// ---------------------------------------------------------------------------
// Kernel 2b: capacity positions + emit dispatch/combine (grid 64).
// pos(token) = counts in earlier chunks (same row) + in-block packed prefix.
// ---------------------------------------------------------------------------
__global__ __launch_bounds__(512) void dispatch_kernel(float* __restrict__ dispatch,
                                                       float* __restrict__ combine) {
    int b = blockIdx.x;
    int row = b >> 3, chunk = b & 7;
    int t = threadIdx.x;
    int lane = t & 31;
    int w = t >> 5;  // 0..15
    __shared__ u64 s_ws[32];
    __shared__ int base8[8];

    int tokr = chunk * 512 + t;
    int gi = row * SS + tokr;
    int e = g_eid[gi];
    float wv = g_w[gi];

    u64 cc0 = (e < 4) ? (1ULL << (e * 16)) : 0ULL;
    u64 cc1 = (e >= 4) ? (1ULL << ((e - 4) * 16)) : 0ULL;
    u64 i0 = cc0, i1 = cc1;
#pragma unroll
    for (int off = 1; off < 32; off <<= 1) {
        u64 n0 = __shfl_up_sync(0xffffffffu, i0, off);
        u64 n1 = __shfl_up_sync(0xffffffffu, i1, off);
        if (lane >= off) { i0 += n0; i1 += n1; }
    }
    if (lane == 31) { s_ws[w] = i0; s_ws[16 + w] = i1; }
    if (t < 8) {
        int s = 0;
        for (int c = 0; c < chunk; c++) s += g_cnt[(row * 8 + c) * 8 + t];
        base8[t] = s;
    }
    __syncthreads();
    if (t == 0) {
        u64 a0 = 0, a1 = 0;
        for (int ww = 0; ww < 16; ww++) {
            u64 x0 = s_ws[ww], x1 = s_ws[16 + ww];
            s_ws[ww] = a0; s_ws[16 + ww] = a1;
            a0 += x0; a1 += x1;
        }
    }
    __syncthreads();
    u64 ex0 = s_ws[w] + i0 - cc0;
    u64 ex1 = s_ws[16 + w] + i1 - cc1;
    int pref = (e < 4) ? (int)((ex0 >> (e * 16)) & 0xffff)
                       : (int)((ex1 >> ((e - 4) * 16)) & 0xffff);
    int pos = base8[e] + pref;
    float keep = (pos < CAP) ? 1.f : 0.f;
    float cw = keep * wv;

    float4* dO = (float4*)(dispatch + (size_t)gi * 8);
    float4* cO = (float4*)(combine + (size_t)gi * 8);
    dO[0] = make_float4(e == 0 ? keep : 0.f, e == 1 ? keep : 0.f,
                        e == 2 ? keep : 0.f, e == 3 ? keep : 0.f);
    dO[1] = make_float4(e == 4 ? keep : 0.f, e == 5 ? keep : 0.f,
                        e == 6 ? keep : 0.f, e == 7 ? keep : 0.f);
    cO[0] = make_float4(e == 0 ? cw : 0.f, e == 1 ? cw : 0.f,
                        e == 2 ? cw : 0.f, e == 3 ? cw : 0.f);
    cO[1] = make_float4(e == 4 ? cw : 0.f, e == 5 ? cw : 0.f,
                        e == 6 ? cw : 0.f, e == 7 ? cw : 0.f);
}

extern "C" void kernel_launch(void* const* d_in, const int* in_sizes, int n_in,
                              void* d_out, int out_size) {
    (void)in_sizes; (void)n_in; (void)out_size;
    const float* hid = (const float*)d_in[0];
    const float* W = (const float*)d_in[1];
    float* out = (float*)d_out;

    float* dispatch = out;
    float* combine = out + (size_t)DD;
    float* probs = out + 2 * (size_t)DD;

    cudaFuncSetAttribute(router_kernel, cudaFuncAttributeMaxDynamicSharedMemorySize, SMEM_BYTES);

    router_kernel<<<K1_GRID, 256, SMEM_BYTES>>>(hid, W, probs);
    argmax_kernel<<<64, 512>>>(probs, out);
    dispatch_kernel<<<64, 512>>>(dispatch, combine);
}

// round 17
// speedup vs baseline: 1.5582x; 1.5582x over previous
#include <cuda_runtime.h>
#include <cuda_pipeline.h>

#define SS 4096
#define HH 2048
#define EE 8
#define CAP 512
#define NTOK 32768
#define DD (NTOK*EE)          /* 262144 */
#define K1_GRID 256           /* 256 blocks x 128 tokens */
#define SMEM_BYTES (65536 + 49152)   /* W 64KB + 8 warps x 3 stages x 2KB = 112KB */

typedef unsigned long long u64;

__device__ float g_part[1024];          // per-K1-block loss partials (512 used)
__device__ unsigned char g_eid[NTOK];   // argmax expert per token
__device__ float g_w[NTOK];             // max prob per token
__device__ int g_cnt[64 * 8];           // [row*8+chunk][expert] counts

__device__ __forceinline__ void ffma2(u64 &acc, u64 a, u64 b) {
    asm("fma.rn.f32x2 %0, %1, %2, %0;" : "+l"(acc) : "l"(a), "l"(b));
}
__device__ __forceinline__ u64 packf2(float a, float b) {
    return (u64)__float_as_uint(a) | ((u64)__float_as_uint(b) << 32);
}
__device__ __forceinline__ float f_lo(u64 v) { return __uint_as_float((unsigned)v); }
__device__ __forceinline__ float f_hi(u64 v) { return __uint_as_float((unsigned)(v >> 32)); }

__device__ __forceinline__ void token_epilogue(const float* lg, float* __restrict__ probs_out,
                                               long tok, float& aux, float& zz) {
    float m = lg[0];
#pragma unroll
    for (int e = 1; e < 8; e++) m = fmaxf(m, lg[e]);
    float p[8];
    float s = 0.f;
#pragma unroll
    for (int e = 0; e < 8; e++) { p[e] = __expf(lg[e] - m); s += p[e]; }
    float inv = 1.f / s;
    float psq = 0.f;
#pragma unroll
    for (int e = 0; e < 8; e++) { p[e] *= inv; psq += p[e] * p[e]; }
    float4* o = (float4*)(probs_out + (size_t)tok * 8);
    o[0] = make_float4(p[0], p[1], p[2], p[3]);
    o[1] = make_float4(p[4], p[5], p[6], p[7]);
    float lse = m + __logf(s);
    aux += psq;
    zz += lse * lse;
}

// ---------------------------------------------------------------------------
// Kernel 1: logits GEMM + softmax + probs + loss partials.
// grid 256, block 256. Block = 128 tokens; warp owns 16 tokens.
// PER-WARP 3-stage cp.async ring (2KB stages) — no block barriers in the
// main loop, warps free-run. W resident in smem (paired f32x2 layout).
// ---------------------------------------------------------------------------
__global__ __launch_bounds__(256, 2) void router_kernel(const float* __restrict__ hid,
                                                        const float* __restrict__ W,
                                                        float* __restrict__ probs_out) {
    extern __shared__ ulonglong2 smem[];
    ulonglong2* swp = smem;               // [e*512 + q]: W[4q..4q+3][e] (64KB)
    ulonglong2* sh  = smem + 4096;        // per-warp rings: [warp][stage][tok16][seg8]

    int tid  = threadIdx.x;
    int lane = tid & 31;
    int wid  = tid >> 5;          // 0..7
    int kseg = tid & 7;
    int sl   = (tid >> 3) & 3;    // slot within warp (token quad)
    long tokB = (long)blockIdx.x * 128;
    const float* hbase = hid + (size_t)tokB * HH;
    const float* wbase = hbase + (size_t)wid * 16 * HH;   // warp's 16 tokens

    ulonglong2* ring = sh + wid * 3 * 128;   // 3 stages x 128 ull2

    // stage s: 16 tokens x 32 floats (h-chunk [s*32, s*32+32)); 4 x 16B per lane
    auto load_stage = [&](int s) {
        ulonglong2* dst = ring + (s % 3) * 128;
#pragma unroll
        for (int k = 0; k < 4; k++) {
            int idx = lane + k * 32;          // 0..127
            int tokloc = idx >> 3;
            int seg = idx & 7;
            __pipeline_memcpy_async(&dst[tokloc * 8 + seg],
                                    wbase + (size_t)tokloc * HH + s * 32 + seg * 4, 16);
        }
        __pipeline_commit();
    };

    // prologue: 3 stages in flight before anything else touches DRAM order
    load_stage(0);
    load_stage(1);
    load_stage(2);

    // W paired layout (one-time)
    for (int idx = tid; idx < 4096; idx += 256) {
        int e = idx >> 9;
        int q = idx & 511;
        int h = q * 4;
        ulonglong2 v;
        v.x = packf2(W[(h + 0) * 8 + e], W[(h + 1) * 8 + e]);
        v.y = packf2(W[(h + 2) * 8 + e], W[(h + 3) * 8 + e]);
        swp[idx] = v;
    }
    __syncthreads();   // only barrier: W ready (rings are warp-private)

    u64 acc0[8] = {0,0,0,0,0,0,0,0};
    u64 acc1[8] = {0,0,0,0,0,0,0,0};
    u64 acc2[8] = {0,0,0,0,0,0,0,0};
    u64 acc3[8] = {0,0,0,0,0,0,0,0};

    for (int i = 0; i < 64; i++) {
        __pipeline_wait_prior(2);             // stage i complete (per-thread)
        const ulonglong2* st = ring + (i % 3) * 128;
        ulonglong2 c0 = st[(4 * sl + 0) * 8 + kseg];
        ulonglong2 c1 = st[(4 * sl + 1) * 8 + kseg];
        ulonglong2 c2 = st[(4 * sl + 2) * 8 + kseg];
        ulonglong2 c3 = st[(4 * sl + 3) * 8 + kseg];

        // refill ring slot (i+3)%3 == i%3 buffer; LDS above already latched.
        if (i + 3 < 64) load_stage(i + 3);
        else            __pipeline_commit();  // empty group keeps wait math uniform

        const ulonglong2* ws = &swp[kseg + 8 * i];
#pragma unroll
        for (int e = 0; e < 8; e++) {
            ulonglong2 w = ws[e * 512];
            ffma2(acc0[e], c0.x, w.x);  ffma2(acc0[e], c0.y, w.y);
            ffma2(acc1[e], c1.x, w.x);  ffma2(acc1[e], c1.y, w.y);
            ffma2(acc2[e], c2.x, w.x);  ffma2(acc2[e], c2.y, w.y);
            ffma2(acc3[e], c3.x, w.x);  ffma2(acc3[e], c3.y, w.y);
        }
    }

    float lg0[8], lg1[8], lg2[8], lg3[8];
#pragma unroll
    for (int e = 0; e < 8; e++) {
        lg0[e] = f_lo(acc0[e]) + f_hi(acc0[e]);
        lg1[e] = f_lo(acc1[e]) + f_hi(acc1[e]);
        lg2[e] = f_lo(acc2[e]) + f_hi(acc2[e]);
        lg3[e] = f_lo(acc3[e]) + f_hi(acc3[e]);
    }
#pragma unroll
    for (int off = 4; off; off >>= 1) {
#pragma unroll
        for (int e = 0; e < 8; e++) {
            lg0[e] += __shfl_down_sync(0xffffffffu, lg0[e], off, 8);
            lg1[e] += __shfl_down_sync(0xffffffffu, lg1[e], off, 8);
            lg2[e] += __shfl_down_sync(0xffffffffu, lg2[e], off, 8);
            lg3[e] += __shfl_down_sync(0xffffffffu, lg3[e], off, 8);
        }
    }

    float auxAcc = 0.f, zAcc = 0.f;
    if (kseg == 0) {
        long tok0 = tokB + (long)(wid * 4 + sl) * 4;
        token_epilogue(lg0, probs_out, tok0 + 0, auxAcc, zAcc);
        token_epilogue(lg1, probs_out, tok0 + 1, auxAcc, zAcc);
        token_epilogue(lg2, probs_out, tok0 + 2, auxAcc, zAcc);
        token_epilogue(lg3, probs_out, tok0 + 3, auxAcc, zAcc);
    }

#pragma unroll
    for (int off = 16; off; off >>= 1) {
        auxAcc += __shfl_down_sync(0xffffffffu, auxAcc, off);
        zAcc   += __shfl_down_sync(0xffffffffu, zAcc, off);
    }
    __shared__ float sA[8], sB[8];
    if (lane == 0) { sA[wid] = auxAcc; sB[wid] = zAcc; }
    __syncthreads();
    if (tid == 0) {
        float a = 0.f, z = 0.f;
#pragma unroll
        for (int w = 0; w < 8; w++) { a += sA[w]; z += sB[w]; }
        g_part[blockIdx.x * 2 + 0] = a;
        g_part[blockIdx.x * 2 + 1] = z;
    }
}

// ---------------------------------------------------------------------------
// Kernel 2a: argmax + per-chunk expert counts (grid 64 = 8 rows x 8 chunks),
// plus fused loss reduction in block 0.
// ---------------------------------------------------------------------------
__global__ __launch_bounds__(512) void argmax_kernel(const float* __restrict__ probs,
                                                     float* __restrict__ out) {
    int b = blockIdx.x;
    int row = b >> 3, chunk = b & 7;
    int t = threadIdx.x;
    __shared__ int scnt[8];
    if (t < 8) scnt[t] = 0;
    __syncthreads();

    int tokr = chunk * 512 + t;
    int gi = row * SS + tokr;
    const float4* pr = (const float4*)(probs + (size_t)gi * 8);
    float4 lo = pr[0];
    float4 hi = pr[1];
    float v[8] = {lo.x, lo.y, lo.z, lo.w, hi.x, hi.y, hi.z, hi.w};
    float m = v[0];
    int mi = 0;
#pragma unroll
    for (int e = 1; e < 8; e++)
        if (v[e] > m) { m = v[e]; mi = e; }
    g_eid[gi] = (unsigned char)mi;
    g_w[gi] = m;
    atomicAdd(&scnt[mi], 1);
    __syncthreads();
    if (t < 8) g_cnt[b * 8 + t] = scnt[t];

    // fused loss reduction (K1 grid = 256 -> 512 partial floats)
    if (b == 0) {
        __shared__ float rA[256], rB[256];
        if (t < 256) { rA[t] = g_part[t * 2]; rB[t] = g_part[t * 2 + 1]; }
        __syncthreads();
        for (int off = 128; off; off >>= 1) {
            if (t < off) { rA[t] += rA[t + off]; rB[t] += rB[t + off]; }
            __syncthreads();
        }
        if (t == 0) {
            out[3 * (size_t)DD + 0] = rA[0] * ((float)EE / (float)NTOK);  // aux_loss
            out[3 * (size_t)DD + 1] = rB[0] / (float)NTOK;                // z_loss
        }
    }
}

// ---------------------------------------------------------------------------
// Kernel 2b: capacity positions + emit dispatch/combine (grid 64).
// pos(token) = counts in earlier chunks (same row) + in-block packed prefix.
// ---------------------------------------------------------------------------
__global__ __launch_bounds__(512) void dispatch_kernel(float* __restrict__ dispatch,
                                                       float* __restrict__ combine) {
    int b = blockIdx.x;
    int row = b >> 3, chunk = b & 7;
    int t = threadIdx.x;
    int lane = t & 31;
    int w = t >> 5;  // 0..15
    __shared__ u64 s_ws[32];
    __shared__ int base8[8];

    int tokr = chunk * 512 + t;
    int gi = row * SS + tokr;
    int e = g_eid[gi];
    float wv = g_w[gi];

    u64 cc0 = (e < 4) ? (1ULL << (e * 16)) : 0ULL;
    u64 cc1 = (e >= 4) ? (1ULL << ((e - 4) * 16)) : 0ULL;
    u64 i0 = cc0, i1 = cc1;
#pragma unroll
    for (int off = 1; off < 32; off <<= 1) {
        u64 n0 = __shfl_up_sync(0xffffffffu, i0, off);
        u64 n1 = __shfl_up_sync(0xffffffffu, i1, off);
        if (lane >= off) { i0 += n0; i1 += n1; }
    }
    if (lane == 31) { s_ws[w] = i0; s_ws[16 + w] = i1; }
    if (t < 8) {
        int s = 0;
        for (int c = 0; c < chunk; c++) s += g_cnt[(row * 8 + c) * 8 + t];
        base8[t] = s;
    }
    __syncthreads();
    if (t == 0) {
        u64 a0 = 0, a1 = 0;
        for (int ww = 0; ww < 16; ww++) {
            u64 x0 = s_ws[ww], x1 = s_ws[16 + ww];
            s_ws[ww] = a0; s_ws[16 + ww] = a1;
            a0 += x0; a1 += x1;
        }
    }
    __syncthreads();
    u64 ex0 = s_ws[w] + i0 - cc0;
    u64 ex1 = s_ws[16 + w] + i1 - cc1;
    int pref = (e < 4) ? (int)((ex0 >> (e * 16)) & 0xffff)
                       : (int)((ex1 >> ((e - 4) * 16)) & 0xffff);
    int pos = base8[e] + pref;
    float keep = (pos < CAP) ? 1.f : 0.f;
    float cw = keep * wv;

    float4* dO = (float4*)(dispatch + (size_t)gi * 8);
    float4* cO = (float4*)(combine + (size_t)gi * 8);
    dO[0] = make_float4(e == 0 ? keep : 0.f, e == 1 ? keep : 0.f,
                        e == 2 ? keep : 0.f, e == 3 ? keep : 0.f);
    dO[1] = make_float4(e == 4 ? keep : 0.f, e == 5 ? keep : 0.f,
                        e == 6 ? keep : 0.f, e == 7 ? keep : 0.f);
    cO[0] = make_float4(e == 0 ? cw : 0.f, e == 1 ? cw : 0.f,
                        e == 2 ? cw : 0.f, e == 3 ? cw : 0.f);
    cO[1] = make_float4(e == 4 ? cw : 0.f, e == 5 ? cw : 0.f,
                        e == 6 ? cw : 0.f, e == 7 ? cw : 0.f);
}

extern "C" void kernel_launch(void* const* d_in, const int* in_sizes, int n_in,
                              void* d_out, int out_size) {
    (void)in_sizes; (void)n_in; (void)out_size;
    const float* hid = (const float*)d_in[0];
    const float* W = (const float*)d_in[1];
    float* out = (float*)d_out;

    float* dispatch = out;
    float* combine = out + (size_t)DD;
    float* probs = out + 2 * (size_t)DD;

    cudaFuncSetAttribute(router_kernel, cudaFuncAttributeMaxDynamicSharedMemorySize, SMEM_BYTES);

    router_kernel<<<K1_GRID, 256, SMEM_BYTES>>>(hid, W, probs);
    argmax_kernel<<<64, 512>>>(probs, out);
    dispatch_kernel<<<64, 512>>>(dispatch, combine);
}